// round 6
// baseline (speedup 1.0000x reference)
#include <cuda_runtime.h>
#include <cstdint>
#include <math.h>

#define BATCH 4096
#define DM    768
#define NT    124
#define NRT   10240

__constant__ int c_shift[5] = {9, 8, 7, 6, 5};
__constant__ int c_tbase[5] = {0, 4, 12, 28, 60};
__constant__ int c_n[5]     = {4, 8, 16, 32, 64};
__constant__ unsigned long long c_goff[5] = {3145730ull, 3162114ull, 3194882ull, 3260418ull, 3391490ull};

#define SP_OFF  3145728ull
#define ACT_OFF 3145729ull

// ---- static device scratch ----
__device__ __align__(256) float g_Xr[(size_t)BATCH * DM];
__device__ __align__(256) float g_Vr[(size_t)NRT * DM];   // [10240][768] n-major, K rows
__device__ __align__(256) float g_W2[(size_t)DM * NRT];   // [768][10240] d-major, K cols
__device__ __align__(256) float g_Y[(size_t)BATCH * NRT];
__device__ __align__(256) float g_P[4ull * BATCH * DM];
__device__ __align__(16) float g_ENC[NT * DM];
__device__ float g_BIAS[NT];
__device__ __align__(16) float g_GATE[(size_t)BATCH * 128];
__device__ float g_SQV[NT];
__device__ float g_SQU[NT];
__device__ float g_SABS[NT];
__device__ float g_CNT[NT];

struct P5 { const float* p[5]; };

__device__ __forceinline__ void decode_t(int t, int& g, int& tl) {
    if (t < 4)       { g = 0; tl = t; }
    else if (t < 12) { g = 1; tl = t - 4; }
    else if (t < 28) { g = 2; tl = t - 12; }
    else if (t < 60) { g = 3; tl = t - 28; }
    else             { g = 4; tl = t - 60; }
}

__device__ __forceinline__ float blk_reduce256(float v) {
    __shared__ float sh[256];
    int tid = threadIdx.x;
    sh[tid] = v;
    __syncthreads();
    for (int s = 128; s > 0; s >>= 1) {
        if (tid < s) sh[tid] += sh[tid + s];
        __syncthreads();
    }
    float r = sh[0];
    __syncthreads();
    return r;
}

// ---- PTX helpers (baseline sm_80+ PTX only) ----
__device__ __forceinline__ uint32_t smem_u32(const void* p) {
    uint32_t a;
    asm("{ .reg .u64 t; cvta.to.shared.u64 t, %1; cvt.u32.u64 %0, t; }" : "=r"(a) : "l"(p));
    return a;
}
__device__ __forceinline__ float rna_tf32(float x) {
    uint32_t r;
    asm("cvt.rna.tf32.f32 %0, %1;" : "=r"(r) : "f"(x));
    return __uint_as_float(r);
}
__device__ __forceinline__ float4 rna4(float4 v) {
    v.x = rna_tf32(v.x); v.y = rna_tf32(v.y); v.z = rna_tf32(v.z); v.w = rna_tf32(v.w);
    return v;
}
__device__ __forceinline__ void cp16(uint32_t dst, const void* src) {
    asm volatile("cp.async.cg.shared.global [%0], [%1], 16;" :: "r"(dst), "l"(src) : "memory");
}
__device__ __forceinline__ void mma_tf32(float* d, const uint32_t* a, const uint32_t* b) {
    asm volatile("mma.sync.aligned.m16n8k8.row.col.f32.tf32.tf32.f32 "
        "{%0,%1,%2,%3}, {%4,%5,%6,%7}, {%8,%9}, {%0,%1,%2,%3};"
        : "+f"(d[0]), "+f"(d[1]), "+f"(d[2]), "+f"(d[3])
        : "r"(a[0]), "r"(a[1]), "r"(a[2]), "r"(a[3]), "r"(b[0]), "r"(b[1]));
}

// ============== prep kernels ==============
__global__ void prep_enc(P5 E, P5 Bv) {
    int t = blockIdx.x;
    int g, tl; decode_t(t, g, tl);
    const float* src = E.p[g] + (size_t)tl * DM;
    for (int i = threadIdx.x; i < DM; i += blockDim.x)
        g_ENC[t * DM + i] = src[i];
    if (threadIdx.x == 0) g_BIAS[t] = Bv.p[g][tl];
}

__global__ void rnd_x(const float* __restrict__ X) {
    int i4 = blockIdx.x * 256 + threadIdx.x;           // < 786432
    ((float4*)g_Xr)[i4] = rna4(((const float4*)X)[i4]);
}

__global__ void rnd_v(P5 V) {
    int i4 = blockIdx.x * 256 + threadIdx.x;           // < 1966080
    int n = i4 / 192, kq = i4 % 192;
    int g = n >> 11, lr = n & 2047;
    ((float4*)g_Vr)[(size_t)n * 192 + kq] = rna4(((const float4*)V.p[g])[(size_t)lr * 192 + kq]);
}

// one launch for all 5 groups: gridDim = (1536, 5)
__global__ void build_w2(P5 U) {
    int g = blockIdx.y;
    int r = 512 >> g;
    int rq = r >> 2;
    int i4 = blockIdx.x * 256 + threadIdx.x;           // < 393216 per group
    int t = i4 / (DM * rq);
    int rem = i4 % (DM * rq);
    int d = rem / rq, jq = rem % rq;
    float4 v = rna4(((const float4*)U.p[g])[(size_t)(t * DM + d) * rq + jq]);
    ((float4*)g_W2)[(size_t)d * 2560 + (g << 9) + t * rq + jq] = v;
}

// ============== exact f32 side computations ==============
__global__ void norms_kernel(P5 V, P5 U) {
    int t = blockIdx.x;
    int g, tl; decode_t(t, g, tl);
    int r = 512 >> g;
    size_t n = (size_t)r * DM;
    const float* v = V.p[g] + (size_t)tl * n;
    const float* u = U.p[g] + (size_t)tl * n;
    float sv = 0.f, su = 0.f;
    for (size_t i = threadIdx.x; i < n; i += 256) {
        float a = v[i]; sv += a * a;
        float b = u[i]; su += b * b;
    }
    sv = blk_reduce256(sv);
    su = blk_reduce256(su);
    if (threadIdx.x == 0) { g_SQV[t] = sv; g_SQU[t] = su; }
}

__global__ void gate_kernel(const float* __restrict__ X, float* __restrict__ out) {
    __shared__ float xs[32][33];
    __shared__ float es[32][129];
    int tid = threadIdx.x;
    int row = tid & 31, chunk = tid >> 5;
    int brow = blockIdx.x * 32;
    float acc[16];
#pragma unroll
    for (int c = 0; c < 16; c++) acc[c] = 0.f;
    for (int k0 = 0; k0 < DM; k0 += 32) {
        for (int i = tid; i < 32 * 32; i += 256) {
            int rr = i >> 5, kk = i & 31;
            xs[rr][kk] = X[(size_t)(brow + rr) * DM + k0 + kk];
        }
        for (int i = tid; i < NT * 32; i += 256) {
            int t = i >> 5, kk = i & 31;
            es[kk][t] = g_ENC[t * DM + k0 + kk];
        }
        __syncthreads();
#pragma unroll 8
        for (int kk = 0; kk < 32; kk++) {
            float xv = xs[row][kk];
#pragma unroll
            for (int c = 0; c < 16; c++) acc[c] += xv * es[kk][chunk * 16 + c];
        }
        __syncthreads();
    }
    int b = brow + row;
#pragma unroll
    for (int c = 0; c < 16; c++) {
        int t = chunk * 16 + c;
        if (t < NT) {
            float pre = acc[c] - g_BIAS[t];
            float gv  = pre > 0.f ? pre : 0.f;
            g_GATE[(size_t)b * 128 + t] = gv;
            int g, tl; decode_t(t, g, tl);
            out[c_goff[g] + (size_t)b * c_n[g] + tl] = gv;
        }
    }
}

__global__ void gate_stats() {
    int t = blockIdx.x;
    float sa = 0.f, cnt = 0.f;
    for (int b = threadIdx.x; b < BATCH; b += 256) {
        float gg = g_GATE[(size_t)b * 128 + t];
        sa  += fabsf(gg);
        cnt += (gg > 0.f) ? 1.f : 0.f;
    }
    sa  = blk_reduce256(sa);
    cnt = blk_reduce256(cnt);
    if (threadIdx.x == 0) { g_SABS[t] = sa; g_CNT[t] = cnt; }
}

__global__ void finalize_kernel(float* __restrict__ out) {
    int t = threadIdx.x;
    float sp = 0.f, act = 0.f;
    if (t < NT) {
        int g, tl; decode_t(t, g, tl);
        int r = 512 >> g;
        float frob = sqrtf(g_SQU[t] * g_SQV[t]) * rsqrtf((float)(DM * r));
        sp  = tanhf(g_SABS[t] / (float)BATCH) * frob;
        act = g_CNT[t];
    }
    __shared__ float s1[128], s2[128];
    s1[t] = sp; s2[t] = act;
    __syncthreads();
    for (int s = 64; s > 0; s >>= 1) {
        if (t < s) { s1[t] += s1[t + s]; s2[t] += s2[t + s]; }
        __syncthreads();
    }
    if (t == 0) {
        out[SP_OFF]  = s1[0];
        out[ACT_OFF] = s2[0] / (float)BATCH;
    }
}

// ============== mma.sync tf32 GEMMs ==============
// MODE 1: g_Y[m,n] = rna( (Xr @ Vr^T)[m,n] * gate[m,t(n)] )   M=4096 N=10240 K=768
// MODE 2: g_P[z][m,d] = (Y @ W2^T)[m,d], K split 4x2560        M=4096 N=768
// BM=BN=128, BK=32, 256 threads, warp=64x32 (4x4 m16n8k8), 3-stage cp.async,
// 2 CTAs/SM (192KB smem, <=128 regs).
#define STGF 8192                 // floats per stage (As 4096 + Bs 4096)
#define SMEMSZ (3 * STGF * 4)     // 96 KB

template<int MODE>
__global__ void __launch_bounds__(256, 2) gemm_mma() {
    extern __shared__ float sm[];
    const int Kdim = (MODE == 1) ? DM : NRT;
    const int NC   = (MODE == 1) ? 24 : 80;
    const float* __restrict__ A = (MODE == 1) ? g_Xr : g_Y;
    const float* __restrict__ B = (MODE == 1) ? g_Vr : g_W2;
    const int bm = blockIdx.y * 128;
    const int bn = blockIdx.x * 128;
    const int kb0 = (MODE == 2) ? blockIdx.z * 2560 : 0;
    const int tid = threadIdx.x;
    const int lane = tid & 31, w = tid >> 5;
    const int gq = lane >> 2, tig = lane & 3;
    const int wm = w & 1, wn = w >> 1;          // M0 = wm*64, N0 = wn*32

    float c[4][4][4];
#pragma unroll
    for (int i = 0; i < 4; i++)
#pragma unroll
        for (int j = 0; j < 4; j++)
#pragma unroll
            for (int q = 0; q < 4; q++) c[i][j][q] = 0.f;

    const uint32_t smb = smem_u32(sm);

#define LOAD_STAGE(s, cidx) do { \
    uint32_t stb = smb + (uint32_t)(s) * (STGF * 4); \
    int kb = kb0 + (cidx) * 32; \
    _Pragma("unroll") \
    for (int t_ = 0; t_ < 8; t_++) { \
        int idx = tid + t_ * 256; \
        int isB = idx >> 10, rem = idx & 1023; \
        int row = rem >> 3, j = rem & 7; \
        uint32_t dst = stb + (uint32_t)(isB * 16384 + row * 128 + ((j ^ (row & 7)) << 4)); \
        const float* src = (isB ? B + (size_t)(bn + row) * Kdim : A + (size_t)(bm + row) * Kdim) + kb + j * 4; \
        cp16(dst, src); \
    } \
    asm volatile("cp.async.commit_group;" ::: "memory"); \
} while (0)

    LOAD_STAGE(0, 0);
    LOAD_STAGE(1, 1);

    for (int i = 0; i < NC; i++) {
        asm volatile("cp.async.wait_group 1;" ::: "memory");
        __syncthreads();
        if (i + 2 < NC) {
            LOAD_STAGE((i + 2) % 3, i + 2);
        } else {
            asm volatile("cp.async.commit_group;" ::: "memory");
        }
        const uint32_t* Asu = (const uint32_t*)(sm + (i % 3) * STGF);
        const uint32_t* Bsu = Asu + 4096;
#pragma unroll
        for (int ks = 0; ks < 4; ks++) {
            const int k0 = ks * 8 + tig;
            const int sw = gq << 2;
            uint32_t a[4][4], b[4][2];
#pragma unroll
            for (int mt = 0; mt < 4; mt++) {
                int r0 = wm * 64 + mt * 16 + gq;
                a[mt][0] = Asu[r0 * 32 + (k0 ^ sw)];
                a[mt][1] = Asu[(r0 + 8) * 32 + (k0 ^ sw)];
                a[mt][2] = Asu[r0 * 32 + ((k0 + 4) ^ sw)];
                a[mt][3] = Asu[(r0 + 8) * 32 + ((k0 + 4) ^ sw)];
            }
#pragma unroll
            for (int nt = 0; nt < 4; nt++) {
                int rn = wn * 32 + nt * 8 + gq;
                b[nt][0] = Bsu[rn * 32 + (k0 ^ sw)];
                b[nt][1] = Bsu[rn * 32 + ((k0 + 4) ^ sw)];
            }
#pragma unroll
            for (int mt = 0; mt < 4; mt++)
#pragma unroll
                for (int nt = 0; nt < 4; nt++)
                    mma_tf32(c[mt][nt], a[mt], b[nt]);
        }
    }

    // epilogue: c[mt][nt][q] -> row = bm+wm*64+mt*16+gq+(q>>1)*8, col = bn+wn*32+nt*8+2*tig+(q&1)
    if (MODE == 1) {
#pragma unroll
        for (int mt = 0; mt < 4; mt++) {
#pragma unroll
            for (int rr = 0; rr < 2; rr++) {
                int m = bm + wm * 64 + mt * 16 + gq + rr * 8;
                const float* grow = g_GATE + (size_t)m * 128;
                float* yrow = g_Y + (size_t)m * NRT;
#pragma unroll
                for (int nt = 0; nt < 4; nt++) {
                    int colg = bn + wn * 32 + nt * 8 + 2 * tig;
                    int gg = colg >> 11;
                    int t = c_tbase[gg] + ((colg & 2047) >> c_shift[gg]);
                    float gv = grow[t];
                    float2 v;
                    v.x = rna_tf32(c[mt][nt][rr * 2 + 0] * gv);
                    v.y = rna_tf32(c[mt][nt][rr * 2 + 1] * gv);
                    *(float2*)(yrow + colg) = v;
                }
            }
        }
    } else {
        float* P = g_P + (size_t)blockIdx.z * ((size_t)BATCH * DM);
#pragma unroll
        for (int mt = 0; mt < 4; mt++) {
#pragma unroll
            for (int rr = 0; rr < 2; rr++) {
                int m = bm + wm * 64 + mt * 16 + gq + rr * 8;
                float* prow = P + (size_t)m * DM;
#pragma unroll
                for (int nt = 0; nt < 4; nt++) {
                    int colg = bn + wn * 32 + nt * 8 + 2 * tig;
                    float2 v = make_float2(c[mt][nt][rr * 2 + 0], c[mt][nt][rr * 2 + 1]);
                    *(float2*)(prow + colg) = v;
                }
            }
        }
    }
}

__global__ void sum4_kernel(float* __restrict__ OUT) {
    size_t i = (size_t)blockIdx.x * 256 + threadIdx.x;   // < 786432
    const size_t N4 = (size_t)BATCH * DM / 4;
    const float4* p = (const float4*)g_P;
    float4 a = p[i], b = p[i + N4], c = p[i + 2 * N4], d = p[i + 3 * N4];
    ((float4*)OUT)[i] = make_float4(a.x + b.x + c.x + d.x, a.y + b.y + c.y + d.y,
                                    a.z + b.z + c.z + d.z, a.w + b.w + c.w + d.w);
}

// ============== launch ==============
extern "C" void kernel_launch(void* const* d_in, const int* in_sizes, int n_in,
                              void* d_out, int out_size) {
    (void)in_sizes; (void)n_in; (void)out_size;
    const float* x = (const float*)d_in[0];
    P5 V, U, E, Bv;
    for (int g = 0; g < 5; g++) {
        V.p[g]  = (const float*)d_in[1 + 4 * g];
        U.p[g]  = (const float*)d_in[2 + 4 * g];
        E.p[g]  = (const float*)d_in[3 + 4 * g];
        Bv.p[g] = (const float*)d_in[4 + 4 * g];
    }
    float* out = (float*)d_out;

    cudaFuncSetAttribute(gemm_mma<1>, cudaFuncAttributeMaxDynamicSharedMemorySize, SMEMSZ);
    cudaFuncSetAttribute(gemm_mma<2>, cudaFuncAttributeMaxDynamicSharedMemorySize, SMEMSZ);

    prep_enc<<<NT, 256>>>(E, Bv);
    rnd_x<<<3072, 256>>>(x);
    rnd_v<<<7680, 256>>>(V);
    build_w2<<<dim3(1536, 5), 256>>>(U);
    norms_kernel<<<NT, 256>>>(V, U);
    gate_kernel<<<BATCH / 32, 256>>>(x, out);
    gate_stats<<<NT, 256>>>();
    finalize_kernel<<<1, 128>>>(out);

    gemm_mma<1><<<dim3(NRT / 128, BATCH / 128), 256, SMEMSZ>>>();
    gemm_mma<2><<<dim3(DM / 128, BATCH / 128, 4), 256, SMEMSZ>>>();
    sum4_kernel<<<3072, 256>>>(out);
}

// round 8
// speedup vs baseline: 1.3902x; 1.3902x over previous
#include <cuda_runtime.h>
#include <cuda_fp16.h>
#include <cstdint>
#include <math.h>

#define BATCH 4096
#define DM    768
#define NT    124
#define NRT   10240

__constant__ int c_shift[5] = {9, 8, 7, 6, 5};
__constant__ int c_tbase[5] = {0, 4, 12, 28, 60};
__constant__ int c_n[5]     = {4, 8, 16, 32, 64};
__constant__ unsigned long long c_goff[5] = {3145730ull, 3162114ull, 3194882ull, 3260418ull, 3391490ull};

#define SP_OFF  3145728ull
#define ACT_OFF 3145729ull

// ---- static device scratch ----
__device__ __align__(256) __half g_Xh[(size_t)BATCH * DM];
__device__ __align__(256) __half g_Vh[(size_t)NRT * DM];    // [10240][768]
__device__ __align__(256) __half g_W2h[(size_t)DM * NRT];   // [768][10240]
__device__ __align__(256) __half g_Yh[(size_t)BATCH * NRT];
__device__ __align__(256) float g_P[4ull * BATCH * DM];
__device__ __align__(16) float g_ENC[NT * DM];
__device__ float g_BIAS[NT];
__device__ __align__(16) float g_GATE[(size_t)BATCH * 128];
__device__ float g_SQV[NT];
__device__ float g_SQU[NT];
__device__ float g_SABS[NT];
__device__ float g_CNT[NT];

struct P5 { const float* p[5]; };

__device__ __forceinline__ void decode_t(int t, int& g, int& tl) {
    if (t < 4)       { g = 0; tl = t; }
    else if (t < 12) { g = 1; tl = t - 4; }
    else if (t < 28) { g = 2; tl = t - 12; }
    else if (t < 60) { g = 3; tl = t - 28; }
    else             { g = 4; tl = t - 60; }
}

__device__ __forceinline__ float blk_reduce256(float v) {
    __shared__ float sh[256];
    int tid = threadIdx.x;
    sh[tid] = v;
    __syncthreads();
    for (int s = 128; s > 0; s >>= 1) {
        if (tid < s) sh[tid] += sh[tid + s];
        __syncthreads();
    }
    float r = sh[0];
    __syncthreads();
    return r;
}

// ---- PTX helpers (baseline sm_80+ PTX only) ----
__device__ __forceinline__ uint32_t smem_u32(const void* p) {
    uint32_t a;
    asm("{ .reg .u64 t; cvta.to.shared.u64 t, %1; cvt.u32.u64 %0, t; }" : "=r"(a) : "l"(p));
    return a;
}
__device__ __forceinline__ void cp16(uint32_t dst, const void* src) {
    asm volatile("cp.async.cg.shared.global [%0], [%1], 16;" :: "r"(dst), "l"(src) : "memory");
}
__device__ __forceinline__ void mma_f16(float* d, const uint32_t* a, const uint32_t* b) {
    asm volatile("mma.sync.aligned.m16n8k16.row.col.f32.f16.f16.f32 "
        "{%0,%1,%2,%3}, {%4,%5,%6,%7}, {%8,%9}, {%0,%1,%2,%3};"
        : "+f"(d[0]), "+f"(d[1]), "+f"(d[2]), "+f"(d[3])
        : "r"(a[0]), "r"(a[1]), "r"(a[2]), "r"(a[3]), "r"(b[0]), "r"(b[1]));
}
__device__ __forceinline__ uint2 f4_to_h4(float4 v) {
    __half2 h0 = __floats2half2_rn(v.x, v.y);
    __half2 h1 = __floats2half2_rn(v.z, v.w);
    uint2 r;
    r.x = *(uint32_t*)&h0;
    r.y = *(uint32_t*)&h1;
    return r;
}

// ============== prep kernels ==============
__global__ void prep_enc(P5 E, P5 Bv) {
    int t = blockIdx.x;
    int g, tl; decode_t(t, g, tl);
    const float* src = E.p[g] + (size_t)tl * DM;
    for (int i = threadIdx.x; i < DM; i += blockDim.x)
        g_ENC[t * DM + i] = src[i];
    if (threadIdx.x == 0) g_BIAS[t] = Bv.p[g][tl];
}

__global__ void rnd_x(const float* __restrict__ X) {
    int i4 = blockIdx.x * 256 + threadIdx.x;           // < 786432
    ((uint2*)g_Xh)[i4] = f4_to_h4(((const float4*)X)[i4]);
}

__global__ void rnd_v(P5 V) {
    int i4 = blockIdx.x * 256 + threadIdx.x;           // < 1966080
    int n = i4 / 192, kq = i4 % 192;
    int g = n >> 11, lr = n & 2047;
    ((uint2*)g_Vh)[(size_t)n * 192 + kq] = f4_to_h4(((const float4*)V.p[g])[(size_t)lr * 192 + kq]);
}

// one launch for all 5 groups: gridDim = (1536, 5)
__global__ void build_w2(P5 U) {
    int g = blockIdx.y;
    int r = 512 >> g;
    int rq = r >> 2;
    int i4 = blockIdx.x * 256 + threadIdx.x;           // < 393216 per group
    int t = i4 / (DM * rq);
    int rem = i4 % (DM * rq);
    int d = rem / rq, jq = rem % rq;
    float4 v = ((const float4*)U.p[g])[(size_t)(t * DM + d) * rq + jq];
    ((uint2*)g_W2h)[(size_t)d * 2560 + (g << 9) + t * rq + jq] = f4_to_h4(v);
}

// ============== exact f32 side computations ==============
__global__ void norms_kernel(P5 V, P5 U) {
    int t = blockIdx.x;
    int g, tl; decode_t(t, g, tl);
    int r = 512 >> g;
    size_t n = (size_t)r * DM;
    const float* v = V.p[g] + (size_t)tl * n;
    const float* u = U.p[g] + (size_t)tl * n;
    float sv = 0.f, su = 0.f;
    for (size_t i = threadIdx.x; i < n; i += 256) {
        float a = v[i]; sv += a * a;
        float b = u[i]; su += b * b;
    }
    sv = blk_reduce256(sv);
    su = blk_reduce256(su);
    if (threadIdx.x == 0) { g_SQV[t] = sv; g_SQU[t] = su; }
}

__global__ void gate_kernel(const float* __restrict__ X, float* __restrict__ out) {
    __shared__ float xs[32][33];
    __shared__ float es[32][129];
    int tid = threadIdx.x;
    int row = tid & 31, chunk = tid >> 5;
    int brow = blockIdx.x * 32;
    float acc[16];
#pragma unroll
    for (int c = 0; c < 16; c++) acc[c] = 0.f;
    for (int k0 = 0; k0 < DM; k0 += 32) {
        for (int i = tid; i < 32 * 32; i += 256) {
            int rr = i >> 5, kk = i & 31;
            xs[rr][kk] = X[(size_t)(brow + rr) * DM + k0 + kk];
        }
        for (int i = tid; i < NT * 32; i += 256) {
            int t = i >> 5, kk = i & 31;
            es[kk][t] = g_ENC[t * DM + k0 + kk];
        }
        __syncthreads();
#pragma unroll 8
        for (int kk = 0; kk < 32; kk++) {
            float xv = xs[row][kk];
#pragma unroll
            for (int c = 0; c < 16; c++) acc[c] += xv * es[kk][chunk * 16 + c];
        }
        __syncthreads();
    }
    int b = brow + row;
#pragma unroll
    for (int c = 0; c < 16; c++) {
        int t = chunk * 16 + c;
        if (t < NT) {
            float pre = acc[c] - g_BIAS[t];
            float gv  = pre > 0.f ? pre : 0.f;
            g_GATE[(size_t)b * 128 + t] = gv;
            int g, tl; decode_t(t, g, tl);
            out[c_goff[g] + (size_t)b * c_n[g] + tl] = gv;
        }
    }
}

__global__ void gate_stats() {
    int t = blockIdx.x;
    float sa = 0.f, cnt = 0.f;
    for (int b = threadIdx.x; b < BATCH; b += 256) {
        float gg = g_GATE[(size_t)b * 128 + t];
        sa  += fabsf(gg);
        cnt += (gg > 0.f) ? 1.f : 0.f;
    }
    sa  = blk_reduce256(sa);
    cnt = blk_reduce256(cnt);
    if (threadIdx.x == 0) { g_SABS[t] = sa; g_CNT[t] = cnt; }
}

__global__ void finalize_kernel(float* __restrict__ out) {
    int t = threadIdx.x;
    float sp = 0.f, act = 0.f;
    if (t < NT) {
        int g, tl; decode_t(t, g, tl);
        int r = 512 >> g;
        float frob = sqrtf(g_SQU[t] * g_SQV[t]) * rsqrtf((float)(DM * r));
        sp  = tanhf(g_SABS[t] / (float)BATCH) * frob;
        act = g_CNT[t];
    }
    __shared__ float s1[128], s2[128];
    s1[t] = sp; s2[t] = act;
    __syncthreads();
    for (int s = 64; s > 0; s >>= 1) {
        if (t < s) { s1[t] += s1[t + s]; s2[t] += s2[t + s]; }
        __syncthreads();
    }
    if (t == 0) {
        out[SP_OFF]  = s1[0];
        out[ACT_OFF] = s2[0] / (float)BATCH;
    }
}

// ============== fp16 mma.sync GEMMs ==============
// MODE 1: Yh[m,n] = h( (Xh @ Vh^T)[m,n] * gate[m,t(n)] )   M=4096 N=10240 K=768
// MODE 2: P[z][m,d] = (Yh @ W2h^T)[m,d], K split 4x2560     M=4096 N=768
// BM=BN=128, BK=64 (fp16: 128B rows), 256 thr, warp 64x32 (4x4 m16n8k16),
// 3-stage cp.async, 2 CTAs/SM. Swizzle: 16B unit u' = u ^ (row&7).
#define STGW 8192                 // 32-bit words per stage (A 4096 + B 4096) = 32KB
#define SMEMSZ (3 * STGW * 4)     // 96 KB

template<int MODE>
__global__ void __launch_bounds__(256, 2) gemm_mma() {
    extern __shared__ uint32_t sm[];
    const int Kdim = (MODE == 1) ? DM : NRT;
    const int NC   = (MODE == 1) ? 12 : 40;
    const __half* __restrict__ A = (MODE == 1) ? g_Xh : g_Yh;
    const __half* __restrict__ B = (MODE == 1) ? g_Vh : g_W2h;
    const int bm = blockIdx.y * 128;
    const int bn = blockIdx.x * 128;
    const int kb0 = (MODE == 2) ? blockIdx.z * 2560 : 0;
    const int tid = threadIdx.x;
    const int lane = tid & 31, w = tid >> 5;
    const int gq = lane >> 2, tig = lane & 3;
    const int wm = w & 1, wn = w >> 1;          // M0 = wm*64, N0 = wn*32

    float c[4][4][4];
#pragma unroll
    for (int i = 0; i < 4; i++)
#pragma unroll
        for (int j = 0; j < 4; j++)
#pragma unroll
            for (int q = 0; q < 4; q++) c[i][j][q] = 0.f;

    const uint32_t smb = smem_u32(sm);

#define LOAD_STAGE(s, cidx) do { \
    uint32_t stb = smb + (uint32_t)(s) * (STGW * 4); \
    int kb = kb0 + (cidx) * 64; \
    _Pragma("unroll") \
    for (int t_ = 0; t_ < 8; t_++) { \
        int idx = tid + t_ * 256; \
        int isB = idx >> 10, rem = idx & 1023; \
        int row = rem >> 3, u = rem & 7; \
        uint32_t dst = stb + (uint32_t)(isB * 16384 + row * 128 + ((u ^ (row & 7)) << 4)); \
        const __half* src = (isB ? B + (size_t)(bn + row) * Kdim : A + (size_t)(bm + row) * Kdim) + kb + u * 8; \
        cp16(dst, src); \
    } \
    asm volatile("cp.async.commit_group;" ::: "memory"); \
} while (0)

    LOAD_STAGE(0, 0);
    LOAD_STAGE(1, 1);

    for (int i = 0; i < NC; i++) {
        asm volatile("cp.async.wait_group 1;" ::: "memory");
        __syncthreads();
        if (i + 2 < NC) {
            LOAD_STAGE((i + 2) % 3, i + 2);
        } else {
            asm volatile("cp.async.commit_group;" ::: "memory");
        }
        const uint32_t* Asu = sm + (i % 3) * STGW;
        const uint32_t* Bsu = Asu + 4096;
#pragma unroll
        for (int ks = 0; ks < 4; ks++) {
            uint32_t a[4][4], b[4][2];
#pragma unroll
            for (int mt = 0; mt < 4; mt++) {
                int r0 = wm * 64 + mt * 16 + gq;
                int sw = r0 & 7;
                int u0 = ((2 * ks) ^ sw) << 2, u1 = ((2 * ks + 1) ^ sw) << 2;
                a[mt][0] = Asu[r0 * 32 + u0 + tig];
                a[mt][1] = Asu[(r0 + 8) * 32 + u0 + tig];
                a[mt][2] = Asu[r0 * 32 + u1 + tig];
                a[mt][3] = Asu[(r0 + 8) * 32 + u1 + tig];
            }
#pragma unroll
            for (int nt = 0; nt < 4; nt++) {
                int rn = wn * 32 + nt * 8 + gq;
                int sw = rn & 7;
                b[nt][0] = Bsu[rn * 32 + (((2 * ks) ^ sw) << 2) + tig];
                b[nt][1] = Bsu[rn * 32 + (((2 * ks + 1) ^ sw) << 2) + tig];
            }
#pragma unroll
            for (int mt = 0; mt < 4; mt++)
#pragma unroll
                for (int nt = 0; nt < 4; nt++)
                    mma_f16(c[mt][nt], a[mt], b[nt]);
        }
    }

    // epilogue: c[mt][nt][q] -> row = bm+wm*64+mt*16+gq+(q>>1)*8, col = bn+wn*32+nt*8+2*tig+(q&1)
    if (MODE == 1) {
#pragma unroll
        for (int mt = 0; mt < 4; mt++) {
#pragma unroll
            for (int rr = 0; rr < 2; rr++) {
                int m = bm + wm * 64 + mt * 16 + gq + rr * 8;
                const float* grow = g_GATE + (size_t)m * 128;
                __half* yrow = g_Yh + (size_t)m * NRT;
#pragma unroll
                for (int nt = 0; nt < 4; nt++) {
                    int colg = bn + wn * 32 + nt * 8 + 2 * tig;
                    int gg = colg >> 11;
                    int t = c_tbase[gg] + ((colg & 2047) >> c_shift[gg]);
                    float gv = grow[t];
                    *(__half2*)(yrow + colg) =
                        __floats2half2_rn(c[mt][nt][rr * 2 + 0] * gv, c[mt][nt][rr * 2 + 1] * gv);
                }
            }
        }
    } else {
        float* P = g_P + (size_t)blockIdx.z * ((size_t)BATCH * DM);
#pragma unroll
        for (int mt = 0; mt < 4; mt++) {
#pragma unroll
            for (int rr = 0; rr < 2; rr++) {
                int m = bm + wm * 64 + mt * 16 + gq + rr * 8;
                float* prow = P + (size_t)m * DM;
#pragma unroll
                for (int nt = 0; nt < 4; nt++) {
                    int colg = bn + wn * 32 + nt * 8 + 2 * tig;
                    *(float2*)(prow + colg) =
                        make_float2(c[mt][nt][rr * 2 + 0], c[mt][nt][rr * 2 + 1]);
                }
            }
        }
    }
}

__global__ void sum4_kernel(float* __restrict__ OUT) {
    size_t i = (size_t)blockIdx.x * 256 + threadIdx.x;   // < 786432
    const size_t N4 = (size_t)BATCH * DM / 4;
    const float4* p = (const float4*)g_P;
    float4 a = p[i], b = p[i + N4], c = p[i + 2 * N4], d = p[i + 3 * N4];
    ((float4*)OUT)[i] = make_float4(a.x + b.x + c.x + d.x, a.y + b.y + c.y + d.y,
                                    a.z + b.z + c.z + d.z, a.w + b.w + c.w + d.w);
}

// ============== launch ==============
extern "C" void kernel_launch(void* const* d_in, const int* in_sizes, int n_in,
                              void* d_out, int out_size) {
    (void)in_sizes; (void)n_in; (void)out_size;
    const float* x = (const float*)d_in[0];
    P5 V, U, E, Bv;
    for (int g = 0; g < 5; g++) {
        V.p[g]  = (const float*)d_in[1 + 4 * g];
        U.p[g]  = (const float*)d_in[2 + 4 * g];
        E.p[g]  = (const float*)d_in[3 + 4 * g];
        Bv.p[g] = (const float*)d_in[4 + 4 * g];
    }
    float* out = (float*)d_out;

    cudaFuncSetAttribute(gemm_mma<1>, cudaFuncAttributeMaxDynamicSharedMemorySize, SMEMSZ);
    cudaFuncSetAttribute(gemm_mma<2>, cudaFuncAttributeMaxDynamicSharedMemorySize, SMEMSZ);

    rnd_x<<<3072, 256>>>(x);
    rnd_v<<<7680, 256>>>(V);
    prep_enc<<<NT, 256>>>(E, Bv);
    gate_kernel<<<BATCH / 32, 256>>>(x, out);
    gemm_mma<1><<<dim3(NRT / 128, BATCH / 128), 256, SMEMSZ>>>();
    build_w2<<<dim3(1536, 5), 256>>>(U);
    norms_kernel<<<NT, 256>>>(V, U);
    gate_stats<<<NT, 256>>>();
    finalize_kernel<<<1, 128>>>(out);
    gemm_mma<2><<<dim3(DM / 128, BATCH / 128, 4), 256, SMEMSZ>>>();
    sum4_kernel<<<3072, 256>>>(out);
}

// round 9
// speedup vs baseline: 1.5470x; 1.1128x over previous
#include <cuda_runtime.h>
#include <cuda_fp16.h>
#include <cstdint>
#include <math.h>

#define BATCH 4096
#define DM    768
#define NT    124
#define NRT   10240

__constant__ int c_shift[5] = {9, 8, 7, 6, 5};
__constant__ int c_tbase[5] = {0, 4, 12, 28, 60};
__constant__ int c_n[5]     = {4, 8, 16, 32, 64};
__constant__ unsigned long long c_goff[5] = {3145730ull, 3162114ull, 3194882ull, 3260418ull, 3391490ull};

#define SP_OFF  3145728ull
#define ACT_OFF 3145729ull

// ---- static device scratch ----
__device__ __align__(256) __half g_Xh[(size_t)BATCH * DM];
__device__ __align__(256) __half g_Vh[(size_t)NRT * DM];    // [10240][768]
__device__ __align__(256) __half g_W2h[(size_t)DM * NRT];   // [768][10240]
__device__ __align__(256) __half g_Yh[(size_t)BATCH * NRT];
__device__ __align__(256) __half g_ENCh[128 * DM];          // 124 rows + 4 zero rows
__device__ __align__(256) float g_P[4ull * BATCH * DM];
__device__ float g_BIAS[NT];
__device__ __align__(16) float g_GATE[(size_t)BATCH * 128];
__device__ float g_SQV[NT];
__device__ float g_SQU[NT];
__device__ float g_SABS[NT];
__device__ float g_CNT[NT];

struct P5 { const float* p[5]; };

__device__ __forceinline__ void decode_t(int t, int& g, int& tl) {
    if (t < 4)       { g = 0; tl = t; }
    else if (t < 12) { g = 1; tl = t - 4; }
    else if (t < 28) { g = 2; tl = t - 12; }
    else if (t < 60) { g = 3; tl = t - 28; }
    else             { g = 4; tl = t - 60; }
}

__device__ __forceinline__ float blk_reduce256(float v) {
    __shared__ float sh[256];
    int tid = threadIdx.x;
    sh[tid] = v;
    __syncthreads();
    for (int s = 128; s > 0; s >>= 1) {
        if (tid < s) sh[tid] += sh[tid + s];
        __syncthreads();
    }
    float r = sh[0];
    __syncthreads();
    return r;
}

// ---- PTX helpers (baseline sm_80+ PTX only) ----
__device__ __forceinline__ uint32_t smem_u32(const void* p) {
    uint32_t a;
    asm("{ .reg .u64 t; cvta.to.shared.u64 t, %1; cvt.u32.u64 %0, t; }" : "=r"(a) : "l"(p));
    return a;
}
__device__ __forceinline__ void cp16(uint32_t dst, const void* src) {
    asm volatile("cp.async.cg.shared.global [%0], [%1], 16;" :: "r"(dst), "l"(src) : "memory");
}
__device__ __forceinline__ void mma_f16(float* d, const uint32_t* a, const uint32_t* b) {
    asm volatile("mma.sync.aligned.m16n8k16.row.col.f32.f16.f16.f32 "
        "{%0,%1,%2,%3}, {%4,%5,%6,%7}, {%8,%9}, {%0,%1,%2,%3};"
        : "+f"(d[0]), "+f"(d[1]), "+f"(d[2]), "+f"(d[3])
        : "r"(a[0]), "r"(a[1]), "r"(a[2]), "r"(a[3]), "r"(b[0]), "r"(b[1]));
}
__device__ __forceinline__ uint2 f4_to_h4(float4 v) {
    __half2 h0 = __floats2half2_rn(v.x, v.y);
    __half2 h1 = __floats2half2_rn(v.z, v.w);
    uint2 r;
    r.x = *(uint32_t*)&h0;
    r.y = *(uint32_t*)&h1;
    return r;
}

// ============== prep kernels ==============
// grid 128: rows 0..123 copy enc (fp16), rows 124..127 zero-fill
__global__ void prep_enc(P5 E, P5 Bv) {
    int t = blockIdx.x;
    if (t < NT) {
        int g, tl; decode_t(t, g, tl);
        const float* src = E.p[g] + (size_t)tl * DM;
        for (int i = threadIdx.x; i < DM; i += blockDim.x)
            g_ENCh[t * DM + i] = __float2half_rn(src[i]);
        if (threadIdx.x == 0) g_BIAS[t] = Bv.p[g][tl];
    } else {
        for (int i = threadIdx.x; i < DM; i += blockDim.x)
            g_ENCh[t * DM + i] = __float2half_rn(0.f);
    }
}

__global__ void rnd_x(const float* __restrict__ X) {
    int i4 = blockIdx.x * 256 + threadIdx.x;           // < 786432
    ((uint2*)g_Xh)[i4] = f4_to_h4(((const float4*)X)[i4]);
}

__global__ void rnd_v(P5 V) {
    int i4 = blockIdx.x * 256 + threadIdx.x;           // < 1966080
    int n = i4 / 192, kq = i4 % 192;
    int g = n >> 11, lr = n & 2047;
    ((uint2*)g_Vh)[(size_t)n * 192 + kq] = f4_to_h4(((const float4*)V.p[g])[(size_t)lr * 192 + kq]);
}

__global__ void build_w2(P5 U) {
    int g = blockIdx.y;
    int r = 512 >> g;
    int rq = r >> 2;
    int i4 = blockIdx.x * 256 + threadIdx.x;           // < 393216 per group
    int t = i4 / (DM * rq);
    int rem = i4 % (DM * rq);
    int d = rem / rq, jq = rem % rq;
    float4 v = ((const float4*)U.p[g])[(size_t)(t * DM + d) * rq + jq];
    ((uint2*)g_W2h)[(size_t)d * 2560 + (g << 9) + t * rq + jq] = f4_to_h4(v);
}

// ============== exact f32 side computations ==============
__global__ void norms_kernel(P5 V, P5 U) {
    int t = blockIdx.x;
    int g, tl; decode_t(t, g, tl);
    int r = 512 >> g;
    size_t n = (size_t)r * DM;
    const float* v = V.p[g] + (size_t)tl * n;
    const float* u = U.p[g] + (size_t)tl * n;
    float sv = 0.f, su = 0.f;
    for (size_t i = threadIdx.x; i < n; i += 256) {
        float a = v[i]; sv += a * a;
        float b = u[i]; su += b * b;
    }
    sv = blk_reduce256(sv);
    su = blk_reduce256(su);
    if (threadIdx.x == 0) { g_SQV[t] = sv; g_SQU[t] = su; }
}

__global__ void gate_stats() {
    int t = blockIdx.x;
    float sa = 0.f, cnt = 0.f;
    for (int b = threadIdx.x; b < BATCH; b += 256) {
        float gg = g_GATE[(size_t)b * 128 + t];
        sa  += fabsf(gg);
        cnt += (gg > 0.f) ? 1.f : 0.f;
    }
    sa  = blk_reduce256(sa);
    cnt = blk_reduce256(cnt);
    if (threadIdx.x == 0) { g_SABS[t] = sa; g_CNT[t] = cnt; }
}

__global__ void finalize_kernel(float* __restrict__ out) {
    int t = threadIdx.x;
    float sp = 0.f, act = 0.f;
    if (t < NT) {
        int g, tl; decode_t(t, g, tl);
        int r = 512 >> g;
        float frob = sqrtf(g_SQU[t] * g_SQV[t]) * rsqrtf((float)(DM * r));
        sp  = tanhf(g_SABS[t] / (float)BATCH) * frob;
        act = g_CNT[t];
    }
    __shared__ float s1[128], s2[128];
    s1[t] = sp; s2[t] = act;
    __syncthreads();
    for (int s = 64; s > 0; s >>= 1) {
        if (t < s) { s1[t] += s1[t + s]; s2[t] += s2[t + s]; }
        __syncthreads();
    }
    if (t == 0) {
        out[SP_OFF]  = s1[0];
        out[ACT_OFF] = s2[0] / (float)BATCH;
    }
}

// ============== fp16 mma.sync GEMMs ==============
// MODE 1: Yh[m,n] = h( (Xh @ Vh^T)[m,n] * gate[m,t(n)] )   M=4096 N=10240 K=768
// MODE 2: P[z][m,d] = (Yh @ W2h^T)[m,d], K split 4x2560     M=4096 N=768
// MODE 3: gates = relu(Xh @ ENCh^T - b): writes g_GATE + strided outputs
// BM=BN=128, BK=64, 256 thr, warp 64x32 (4x4 m16n8k16), 3-stage cp.async, 2 CTA/SM.
#define STGW 8192                 // 32-bit words per stage = 32KB
#define SMEMSZ (3 * STGW * 4)     // 96 KB

template<int MODE>
__global__ void __launch_bounds__(256, 2) gemm_mma(float* __restrict__ out) {
    extern __shared__ uint32_t sm[];
    const int Kdim = (MODE == 2) ? NRT : DM;
    const int NC   = (MODE == 2) ? 40 : 12;
    const __half* __restrict__ A = (MODE == 2) ? g_Yh : g_Xh;
    const __half* __restrict__ B = (MODE == 1) ? g_Vh : ((MODE == 2) ? g_W2h : g_ENCh);
    const int bm = blockIdx.y * 128;
    const int bn = blockIdx.x * 128;
    const int kb0 = (MODE == 2) ? blockIdx.z * 2560 : 0;
    const int tid = threadIdx.x;
    const int lane = tid & 31, w = tid >> 5;
    const int gq = lane >> 2, tig = lane & 3;
    const int wm = w & 1, wn = w >> 1;

    float c[4][4][4];
#pragma unroll
    for (int i = 0; i < 4; i++)
#pragma unroll
        for (int j = 0; j < 4; j++)
#pragma unroll
            for (int q = 0; q < 4; q++) c[i][j][q] = 0.f;

    const uint32_t smb = smem_u32(sm);

#define LOAD_STAGE(s, cidx) do { \
    uint32_t stb = smb + (uint32_t)(s) * (STGW * 4); \
    int kb = kb0 + (cidx) * 64; \
    _Pragma("unroll") \
    for (int t_ = 0; t_ < 8; t_++) { \
        int idx = tid + t_ * 256; \
        int isB = idx >> 10, rem = idx & 1023; \
        int row = rem >> 3, u = rem & 7; \
        uint32_t dst = stb + (uint32_t)(isB * 16384 + row * 128 + ((u ^ (row & 7)) << 4)); \
        const __half* src = (isB ? B + (size_t)(bn + row) * Kdim : A + (size_t)(bm + row) * Kdim) + kb + u * 8; \
        cp16(dst, src); \
    } \
    asm volatile("cp.async.commit_group;" ::: "memory"); \
} while (0)

    LOAD_STAGE(0, 0);
    LOAD_STAGE(1, 1);

    for (int i = 0; i < NC; i++) {
        asm volatile("cp.async.wait_group 1;" ::: "memory");
        __syncthreads();
        if (i + 2 < NC) {
            LOAD_STAGE((i + 2) % 3, i + 2);
        } else {
            asm volatile("cp.async.commit_group;" ::: "memory");
        }
        const uint32_t* Asu = sm + (i % 3) * STGW;
        const uint32_t* Bsu = Asu + 4096;
#pragma unroll
        for (int ks = 0; ks < 4; ks++) {
            uint32_t a[4][4], b[4][2];
#pragma unroll
            for (int mt = 0; mt < 4; mt++) {
                int r0 = wm * 64 + mt * 16 + gq;
                int sw = r0 & 7;
                int u0 = ((2 * ks) ^ sw) << 2, u1 = ((2 * ks + 1) ^ sw) << 2;
                a[mt][0] = Asu[r0 * 32 + u0 + tig];
                a[mt][1] = Asu[(r0 + 8) * 32 + u0 + tig];
                a[mt][2] = Asu[r0 * 32 + u1 + tig];
                a[mt][3] = Asu[(r0 + 8) * 32 + u1 + tig];
            }
#pragma unroll
            for (int nt = 0; nt < 4; nt++) {
                int rn = wn * 32 + nt * 8 + gq;
                int sw = rn & 7;
                b[nt][0] = Bsu[rn * 32 + (((2 * ks) ^ sw) << 2) + tig];
                b[nt][1] = Bsu[rn * 32 + (((2 * ks + 1) ^ sw) << 2) + tig];
            }
#pragma unroll
            for (int mt = 0; mt < 4; mt++)
#pragma unroll
                for (int nt = 0; nt < 4; nt++)
                    mma_f16(c[mt][nt], a[mt], b[nt]);
        }
    }

    // epilogue: c[mt][nt][q] -> row = bm+wm*64+mt*16+gq+(q>>1)*8, col = bn+wn*32+nt*8+2*tig+(q&1)
    if (MODE == 1) {
#pragma unroll
        for (int mt = 0; mt < 4; mt++) {
#pragma unroll
            for (int rr = 0; rr < 2; rr++) {
                int m = bm + wm * 64 + mt * 16 + gq + rr * 8;
                const float* grow = g_GATE + (size_t)m * 128;
                __half* yrow = g_Yh + (size_t)m * NRT;
#pragma unroll
                for (int nt = 0; nt < 4; nt++) {
                    int colg = bn + wn * 32 + nt * 8 + 2 * tig;
                    int gg = colg >> 11;
                    int t = c_tbase[gg] + ((colg & 2047) >> c_shift[gg]);
                    float gv = grow[t];
                    *(__half2*)(yrow + colg) =
                        __floats2half2_rn(c[mt][nt][rr * 2 + 0] * gv, c[mt][nt][rr * 2 + 1] * gv);
                }
            }
        }
    } else if (MODE == 2) {
        float* P = g_P + (size_t)blockIdx.z * ((size_t)BATCH * DM);
#pragma unroll
        for (int mt = 0; mt < 4; mt++) {
#pragma unroll
            for (int rr = 0; rr < 2; rr++) {
                int m = bm + wm * 64 + mt * 16 + gq + rr * 8;
                float* prow = P + (size_t)m * DM;
#pragma unroll
                for (int nt = 0; nt < 4; nt++) {
                    int colg = bn + wn * 32 + nt * 8 + 2 * tig;
                    *(float2*)(prow + colg) =
                        make_float2(c[mt][nt][rr * 2 + 0], c[mt][nt][rr * 2 + 1]);
                }
            }
        }
    } else {
        // gates: pre = acc - bias; g = relu(pre); write scratch + grouped outputs
#pragma unroll
        for (int mt = 0; mt < 4; mt++) {
#pragma unroll
            for (int rr = 0; rr < 2; rr++) {
                int m = bm + wm * 64 + mt * 16 + gq + rr * 8;
#pragma unroll
                for (int nt = 0; nt < 4; nt++) {
#pragma unroll
                    for (int e = 0; e < 2; e++) {
                        int t = wn * 32 + nt * 8 + 2 * tig + e;
                        if (t < NT) {
                            float pre = c[mt][nt][rr * 2 + e] - g_BIAS[t];
                            float gv = pre > 0.f ? pre : 0.f;
                            g_GATE[(size_t)m * 128 + t] = gv;
                            int gg, tl; decode_t(t, gg, tl);
                            out[c_goff[gg] + (size_t)m * c_n[gg] + tl] = gv;
                        }
                    }
                }
            }
        }
    }
}

__global__ void sum4_kernel(float* __restrict__ OUT) {
    size_t i = (size_t)blockIdx.x * 256 + threadIdx.x;   // < 786432
    const size_t N4 = (size_t)BATCH * DM / 4;
    const float4* p = (const float4*)g_P;
    float4 a = p[i], b = p[i + N4], c = p[i + 2 * N4], d = p[i + 3 * N4];
    ((float4*)OUT)[i] = make_float4(a.x + b.x + c.x + d.x, a.y + b.y + c.y + d.y,
                                    a.z + b.z + c.z + d.z, a.w + b.w + c.w + d.w);
}

// ============== launch ==============
extern "C" void kernel_launch(void* const* d_in, const int* in_sizes, int n_in,
                              void* d_out, int out_size) {
    (void)in_sizes; (void)n_in; (void)out_size;
    const float* x = (const float*)d_in[0];
    P5 V, U, E, Bv;
    for (int g = 0; g < 5; g++) {
        V.p[g]  = (const float*)d_in[1 + 4 * g];
        U.p[g]  = (const float*)d_in[2 + 4 * g];
        E.p[g]  = (const float*)d_in[3 + 4 * g];
        Bv.p[g] = (const float*)d_in[4 + 4 * g];
    }
    float* out = (float*)d_out;

    cudaFuncSetAttribute(gemm_mma<1>, cudaFuncAttributeMaxDynamicSharedMemorySize, SMEMSZ);
    cudaFuncSetAttribute(gemm_mma<2>, cudaFuncAttributeMaxDynamicSharedMemorySize, SMEMSZ);
    cudaFuncSetAttribute(gemm_mma<3>, cudaFuncAttributeMaxDynamicSharedMemorySize, SMEMSZ);

    rnd_x<<<3072, 256>>>(x);
    prep_enc<<<128, 256>>>(E, Bv);
    rnd_v<<<7680, 256>>>(V);
    gemm_mma<3><<<dim3(1, BATCH / 128), 256, SMEMSZ>>>(out);   // gates
    gemm_mma<1><<<dim3(NRT / 128, BATCH / 128), 256, SMEMSZ>>>(out);
    build_w2<<<dim3(1536, 5), 256>>>(U);
    norms_kernel<<<NT, 256>>>(V, U);
    gate_stats<<<NT, 256>>>();
    finalize_kernel<<<1, 128>>>(out);
    gemm_mma<2><<<dim3(DM / 128, BATCH / 128, 4), 256, SMEMSZ>>>(out);
    sum4_kernel<<<3072, 256>>>(out);
}

// round 11
// speedup vs baseline: 2.6321x; 1.7014x over previous
#include <cuda_runtime.h>
#include <cuda_fp16.h>
#include <cstdint>
#include <math.h>

#define BATCH 4096
#define DM    768
#define NT    124
#define NRT   10240

__constant__ int c_shift[5] = {9, 8, 7, 6, 5};
__constant__ int c_tbase[5] = {0, 4, 12, 28, 60};
__constant__ int c_n[5]     = {4, 8, 16, 32, 64};
__constant__ unsigned long long c_goff[5] = {3145730ull, 3162114ull, 3194882ull, 3260418ull, 3391490ull};

#define SP_OFF  3145728ull
#define ACT_OFF 3145729ull

// ---- static device scratch ----
__device__ __align__(256) __half g_Xh[(size_t)BATCH * DM];
__device__ __align__(256) __half g_Vh[(size_t)NRT * DM];    // [10240][768]
__device__ __align__(256) __half g_W2h[(size_t)DM * NRT];   // [768][10240]
__device__ __align__(256) __half g_Yh[(size_t)BATCH * NRT];
__device__ __align__(256) __half g_ENCh[128 * DM];          // 124 rows + 4 zero rows
__device__ __align__(256) float g_P[5ull * BATCH * DM];
__device__ float g_BIAS[NT];
__device__ __align__(16) float g_GATE[(size_t)BATCH * 128];
__device__ float g_PSQV[320];
__device__ float g_PSQU[320];
__device__ float g_PSABS[32 * 128];
__device__ float g_PCNT[32 * 128];

struct P5 { const float* p[5]; };

__device__ __forceinline__ void decode_t(int t, int& g, int& tl) {
    if (t < 4)       { g = 0; tl = t; }
    else if (t < 12) { g = 1; tl = t - 4; }
    else if (t < 28) { g = 2; tl = t - 12; }
    else if (t < 60) { g = 3; tl = t - 28; }
    else             { g = 4; tl = t - 60; }
}

__device__ __forceinline__ float blk_reduce256(float v) {
    __shared__ float sh[256];
    int tid = threadIdx.x;
    sh[tid] = v;
    __syncthreads();
    for (int s = 128; s > 0; s >>= 1) {
        if (tid < s) sh[tid] += sh[tid + s];
        __syncthreads();
    }
    float r = sh[0];
    __syncthreads();
    return r;
}

// ---- PTX helpers (baseline sm_80+ PTX only) ----
__device__ __forceinline__ uint32_t smem_u32(const void* p) {
    uint32_t a;
    asm("{ .reg .u64 t; cvta.to.shared.u64 t, %1; cvt.u32.u64 %0, t; }" : "=r"(a) : "l"(p));
    return a;
}
__device__ __forceinline__ void cp16(uint32_t dst, const void* src) {
    asm volatile("cp.async.cg.shared.global [%0], [%1], 16;" :: "r"(dst), "l"(src) : "memory");
}
__device__ __forceinline__ void mma_f16(float* d, const uint32_t* a, const uint32_t* b) {
    asm volatile("mma.sync.aligned.m16n8k16.row.col.f32.f16.f16.f32 "
        "{%0,%1,%2,%3}, {%4,%5,%6,%7}, {%8,%9}, {%0,%1,%2,%3};"
        : "+f"(d[0]), "+f"(d[1]), "+f"(d[2]), "+f"(d[3])
        : "r"(a[0]), "r"(a[1]), "r"(a[2]), "r"(a[3]), "r"(b[0]), "r"(b[1]));
}

// ============== prep kernels ==============
// fused: blocks [0,7680) convert V -> fp16; blocks [7680,7808) build ENC fp16 + bias
__global__ void prep_fused(P5 V, P5 E, P5 Bv) {
    int b = blockIdx.x;
    if (b < 7680) {
        int i4 = b * 256 + threadIdx.x;                // < 1966080
        int n = i4 / 192, kq = i4 % 192;
        int g = n >> 11, lr = n & 2047;
        float4 v = ((const float4*)V.p[g])[(size_t)lr * 192 + kq];
        __half2 h0 = __floats2half2_rn(v.x, v.y);
        __half2 h1 = __floats2half2_rn(v.z, v.w);
        uint2 r; r.x = *(uint32_t*)&h0; r.y = *(uint32_t*)&h1;
        ((uint2*)g_Vh)[(size_t)n * 192 + kq] = r;
    } else {
        int t = b - 7680;                              // 0..127
        if (t < NT) {
            int g, tl; decode_t(t, g, tl);
            const float* src = E.p[g] + (size_t)tl * DM;
            for (int i = threadIdx.x; i < DM; i += blockDim.x)
                g_ENCh[t * DM + i] = __float2half_rn(src[i]);
            if (threadIdx.x == 0) g_BIAS[t] = Bv.p[g][tl];
        } else {
            for (int i = threadIdx.x; i < DM; i += blockDim.x)
                g_ENCh[t * DM + i] = __float2half_rn(0.f);
        }
    }
}

__global__ void rnd_x(const float* __restrict__ X) {
    int i4 = blockIdx.x * 256 + threadIdx.x;           // < 786432
    float4 v = ((const float4*)X)[i4];
    __half2 h0 = __floats2half2_rn(v.x, v.y);
    __half2 h1 = __floats2half2_rn(v.z, v.w);
    uint2 r; r.x = *(uint32_t*)&h0; r.y = *(uint32_t*)&h1;
    ((uint2*)g_Xh)[i4] = r;
}

__global__ void build_w2(P5 U) {
    int g = blockIdx.y;
    int r = 512 >> g;
    int rq = r >> 2;
    int i4 = blockIdx.x * 256 + threadIdx.x;           // < 393216 per group
    int t = i4 / (DM * rq);
    int rem = i4 % (DM * rq);
    int d = rem / rq, jq = rem % rq;
    float4 v = ((const float4*)U.p[g])[(size_t)(t * DM + d) * rq + jq];
    __half2 h0 = __floats2half2_rn(v.x, v.y);
    __half2 h1 = __floats2half2_rn(v.z, v.w);
    uint2 rv; rv.x = *(uint32_t*)&h0; rv.y = *(uint32_t*)&h1;
    ((uint2*)g_W2h)[(size_t)d * 2560 + (g << 9) + t * rq + jq] = rv;
}

// ============== balanced norms: 320 segments of 32 rows ==============
__global__ void norms2(P5 V, P5 U) {
    int s = blockIdx.x;                   // 0..319
    int g = s >> 6, idx = s & 63;
    int nseg = 16 >> g;
    int tl = idx / nseg, seg = idx % nseg;
    int r = 512 >> g;
    const float4* v = (const float4*)(V.p[g] + ((size_t)tl * r + seg * 32) * DM);
    const float4* u = (const float4*)(U.p[g] + ((size_t)tl * r + seg * 32) * DM);
    float sv = 0.f, su = 0.f;
    for (int i = threadIdx.x; i < 32 * DM / 4; i += 256) {
        float4 a = v[i]; sv += a.x * a.x + a.y * a.y + a.z * a.z + a.w * a.w;
        float4 b = u[i]; su += b.x * b.x + b.y * b.y + b.z * b.z + b.w * b.w;
    }
    sv = blk_reduce256(sv);
    su = blk_reduce256(su);
    if (threadIdx.x == 0) { g_PSQV[s] = sv; g_PSQU[s] = su; }
}

// ============== coalesced gate stats: 32 blocks x 128 rows ==============
__global__ void gstat2() {
    int tid = threadIdx.x;
    int col = tid & 127, half = tid >> 7;
    int b0 = blockIdx.x * 128;
    float sa = 0.f, cnt = 0.f;
    for (int i = 0; i < 64; i++) {
        float gg = g_GATE[(size_t)(b0 + half + 2 * i) * 128 + col];
        sa += fabsf(gg);
        cnt += (gg > 0.f) ? 1.f : 0.f;
    }
    __shared__ float s1[256], s2[256];
    s1[tid] = sa; s2[tid] = cnt;
    __syncthreads();
    if (half == 0) {
        g_PSABS[blockIdx.x * 128 + col] = s1[tid] + s1[tid + 128];
        g_PCNT[blockIdx.x * 128 + col]  = s2[tid] + s2[tid + 128];
    }
}

__global__ void finalize_kernel(float* __restrict__ out) {
    int t = threadIdx.x;   // 128 threads
    float sp = 0.f, act = 0.f;
    if (t < NT) {
        int g, tl; decode_t(t, g, tl);
        int r = 512 >> g;
        int nseg = 16 >> g;
        int base = g * 64 + tl * nseg;
        float sqv = 0.f, squ = 0.f;
        for (int j = 0; j < nseg; j++) { sqv += g_PSQV[base + j]; squ += g_PSQU[base + j]; }
        float sa = 0.f, cnt = 0.f;
        for (int cck = 0; cck < 32; cck++) { sa += g_PSABS[cck * 128 + t]; cnt += g_PCNT[cck * 128 + t]; }
        float frob = sqrtf(squ * sqv) * rsqrtf((float)(DM * r));
        sp  = tanhf(sa / (float)BATCH) * frob;
        act = cnt;
    }
    __shared__ float s1[128], s2[128];
    s1[t] = sp; s2[t] = act;
    __syncthreads();
    for (int s = 64; s > 0; s >>= 1) {
        if (t < s) { s1[t] += s1[t + s]; s2[t] += s2[t + s]; }
        __syncthreads();
    }
    if (t == 0) {
        out[SP_OFF]  = s1[0];
        out[ACT_OFF] = s2[0] / (float)BATCH;
    }
}

// ============== fp16 mma.sync GEMMs ==============
// MODE 1: Yh[m,n] = h( (Xh @ Vh^T)[m,n] * gate[m,t(n)] )   M=4096 N=10240 K=768
// MODE 2: P[z][m,d] = (Yh @ W2h^T)[m,d], K split 5x2048     M=4096 N=768
// MODE 3: gates = relu(Xh @ ENCh^T - b): writes g_GATE + strided outputs
// BM=BN=128, BK=64, 256 thr, warp 64x32 (4x4 m16n8k16), 3-stage cp.async, 2 CTA/SM.
#define STGW 8192                 // 32-bit words per stage = 32KB
#define SMEMSZ (3 * STGW * 4)     // 96 KB

template<int MODE>
__global__ void __launch_bounds__(256, 2) gemm_mma(float* __restrict__ out) {
    extern __shared__ uint32_t sm[];
    const int Kdim = (MODE == 2) ? NRT : DM;
    const int NC   = (MODE == 2) ? 32 : 12;
    const __half* __restrict__ A = (MODE == 2) ? g_Yh : g_Xh;
    const __half* __restrict__ B = (MODE == 1) ? g_Vh : ((MODE == 2) ? g_W2h : g_ENCh);
    const int bm = blockIdx.y * 128;
    const int bn = blockIdx.x * 128;
    const int kb0 = (MODE == 2) ? blockIdx.z * 2048 : 0;
    const int tid = threadIdx.x;
    const int lane = tid & 31, w = tid >> 5;
    const int gq = lane >> 2, tig = lane & 3;
    const int wm = w & 1, wn = w >> 1;

    float c[4][4][4];
#pragma unroll
    for (int i = 0; i < 4; i++)
#pragma unroll
        for (int j = 0; j < 4; j++)
#pragma unroll
            for (int q = 0; q < 4; q++) c[i][j][q] = 0.f;

    const uint32_t smb = smem_u32(sm);

#define LOAD_STAGE(s, cidx) do { \
    uint32_t stb = smb + (uint32_t)(s) * (STGW * 4); \
    int kb = kb0 + (cidx) * 64; \
    _Pragma("unroll") \
    for (int t_ = 0; t_ < 8; t_++) { \
        int idx = tid + t_ * 256; \
        int isB = idx >> 10, rem = idx & 1023; \
        int row = rem >> 3, u = rem & 7; \
        uint32_t dst = stb + (uint32_t)(isB * 16384 + row * 128 + ((u ^ (row & 7)) << 4)); \
        const __half* src = (isB ? B + (size_t)(bn + row) * Kdim : A + (size_t)(bm + row) * Kdim) + kb + u * 8; \
        cp16(dst, src); \
    } \
    asm volatile("cp.async.commit_group;" ::: "memory"); \
} while (0)

    LOAD_STAGE(0, 0);
    LOAD_STAGE(1, 1);

    for (int i = 0; i < NC; i++) {
        asm volatile("cp.async.wait_group 1;" ::: "memory");
        __syncthreads();
        if (i + 2 < NC) {
            LOAD_STAGE((i + 2) % 3, i + 2);
        } else {
            asm volatile("cp.async.commit_group;" ::: "memory");
        }
        const uint32_t* Asu = sm + (i % 3) * STGW;
        const uint32_t* Bsu = Asu + 4096;
#pragma unroll
        for (int ks = 0; ks < 4; ks++) {
            uint32_t a[4][4], b[4][2];
#pragma unroll
            for (int mt = 0; mt < 4; mt++) {
                int r0 = wm * 64 + mt * 16 + gq;
                int sw = r0 & 7;
                int u0 = ((2 * ks) ^ sw) << 2, u1 = ((2 * ks + 1) ^ sw) << 2;
                a[mt][0] = Asu[r0 * 32 + u0 + tig];
                a[mt][1] = Asu[(r0 + 8) * 32 + u0 + tig];
                a[mt][2] = Asu[r0 * 32 + u1 + tig];
                a[mt][3] = Asu[(r0 + 8) * 32 + u1 + tig];
            }
#pragma unroll
            for (int nt = 0; nt < 4; nt++) {
                int rn = wn * 32 + nt * 8 + gq;
                int sw = rn & 7;
                b[nt][0] = Bsu[rn * 32 + (((2 * ks) ^ sw) << 2) + tig];
                b[nt][1] = Bsu[rn * 32 + (((2 * ks + 1) ^ sw) << 2) + tig];
            }
#pragma unroll
            for (int mt = 0; mt < 4; mt++)
#pragma unroll
                for (int nt = 0; nt < 4; nt++)
                    mma_f16(c[mt][nt], a[mt], b[nt]);
        }
    }

    // epilogue: c[mt][nt][q] -> row = bm+wm*64+mt*16+gq+(q>>1)*8, col = bn+wn*32+nt*8+2*tig+(q&1)
    if (MODE == 1) {
#pragma unroll
        for (int mt = 0; mt < 4; mt++) {
#pragma unroll
            for (int rr = 0; rr < 2; rr++) {
                int m = bm + wm * 64 + mt * 16 + gq + rr * 8;
                const float* grow = g_GATE + (size_t)m * 128;
                __half* yrow = g_Yh + (size_t)m * NRT;
#pragma unroll
                for (int nt = 0; nt < 4; nt++) {
                    int colg = bn + wn * 32 + nt * 8 + 2 * tig;
                    int gg = colg >> 11;
                    int t = c_tbase[gg] + ((colg & 2047) >> c_shift[gg]);
                    float gv = grow[t];
                    *(__half2*)(yrow + colg) =
                        __floats2half2_rn(c[mt][nt][rr * 2 + 0] * gv, c[mt][nt][rr * 2 + 1] * gv);
                }
            }
        }
    } else if (MODE == 2) {
        float* P = g_P + (size_t)blockIdx.z * ((size_t)BATCH * DM);
#pragma unroll
        for (int mt = 0; mt < 4; mt++) {
#pragma unroll
            for (int rr = 0; rr < 2; rr++) {
                int m = bm + wm * 64 + mt * 16 + gq + rr * 8;
                float* prow = P + (size_t)m * DM;
#pragma unroll
                for (int nt = 0; nt < 4; nt++) {
                    int colg = bn + wn * 32 + nt * 8 + 2 * tig;
                    *(float2*)(prow + colg) =
                        make_float2(c[mt][nt][rr * 2 + 0], c[mt][nt][rr * 2 + 1]);
                }
            }
        }
    } else {
#pragma unroll
        for (int mt = 0; mt < 4; mt++) {
#pragma unroll
            for (int rr = 0; rr < 2; rr++) {
                int m = bm + wm * 64 + mt * 16 + gq + rr * 8;
#pragma unroll
                for (int nt = 0; nt < 4; nt++) {
#pragma unroll
                    for (int e = 0; e < 2; e++) {
                        int t = wn * 32 + nt * 8 + 2 * tig + e;
                        if (t < NT) {
                            float pre = c[mt][nt][rr * 2 + e] - g_BIAS[t];
                            float gv = pre > 0.f ? pre : 0.f;
                            g_GATE[(size_t)m * 128 + t] = gv;
                            int gg, tl; decode_t(t, gg, tl);
                            out[c_goff[gg] + (size_t)m * c_n[gg] + tl] = gv;
                        }
                    }
                }
            }
        }
    }
}

__global__ void sum5_kernel(float* __restrict__ OUT) {
    size_t i = (size_t)blockIdx.x * 256 + threadIdx.x;   // < 786432
    const size_t N4 = (size_t)BATCH * DM / 4;
    const float4* p = (const float4*)g_P;
    float4 a = p[i], b = p[i + N4], c = p[i + 2 * N4], d = p[i + 3 * N4], e = p[i + 4 * N4];
    ((float4*)OUT)[i] = make_float4(a.x + b.x + c.x + d.x + e.x, a.y + b.y + c.y + d.y + e.y,
                                    a.z + b.z + c.z + d.z + e.z, a.w + b.w + c.w + d.w + e.w);
}

// ============== launch ==============
extern "C" void kernel_launch(void* const* d_in, const int* in_sizes, int n_in,
                              void* d_out, int out_size) {
    (void)in_sizes; (void)n_in; (void)out_size;
    const float* x = (const float*)d_in[0];
    P5 V, U, E, Bv;
    for (int g = 0; g < 5; g++) {
        V.p[g]  = (const float*)d_in[1 + 4 * g];
        U.p[g]  = (const float*)d_in[2 + 4 * g];
        E.p[g]  = (const float*)d_in[3 + 4 * g];
        Bv.p[g] = (const float*)d_in[4 + 4 * g];
    }
    float* out = (float*)d_out;

    cudaFuncSetAttribute(gemm_mma<1>, cudaFuncAttributeMaxDynamicSharedMemorySize, SMEMSZ);
    cudaFuncSetAttribute(gemm_mma<2>, cudaFuncAttributeMaxDynamicSharedMemorySize, SMEMSZ);
    cudaFuncSetAttribute(gemm_mma<3>, cudaFuncAttributeMaxDynamicSharedMemorySize, SMEMSZ);

    prep_fused<<<7808, 256>>>(V, E, Bv);                         // 0
    rnd_x<<<3072, 256>>>(x);                                     // 1
    gemm_mma<3><<<dim3(1, BATCH / 128), 256, SMEMSZ>>>(out);     // 2: gates
    gemm_mma<1><<<dim3(NRT / 128, BATCH / 128), 256, SMEMSZ>>>(out); // 3: ncu slot
    build_w2<<<dim3(1536, 5), 256>>>(U);                         // 4
    norms2<<<320, 256>>>(V, U);                                  // 5
    gstat2<<<32, 256>>>();                                       // 6
    finalize_kernel<<<1, 128>>>(out);                            // 7
    gemm_mma<2><<<dim3(DM / 128, BATCH / 128, 5), 256, SMEMSZ>>>(out); // 8
    sum5_kernel<<<3072, 256>>>(out);                             // 9
}

// round 13
// speedup vs baseline: 2.8233x; 1.0726x over previous
#include <cuda_runtime.h>
#include <cuda_fp16.h>
#include <cstdint>
#include <math.h>

#define BATCH 4096
#define DM    768
#define NT    124
#define NRT   10240

__constant__ int c_shift[5] = {9, 8, 7, 6, 5};
__constant__ int c_tbase[5] = {0, 4, 12, 28, 60};
__constant__ int c_n[5]     = {4, 8, 16, 32, 64};
__constant__ unsigned long long c_goff[5] = {3145730ull, 3162114ull, 3194882ull, 3260418ull, 3391490ull};

#define SP_OFF  3145728ull
#define ACT_OFF 3145729ull

// ---- static device scratch ----
__device__ __align__(256) __half g_Xh[(size_t)BATCH * DM];
__device__ __align__(256) __half g_Vh[(size_t)NRT * DM];    // [10240][768]
__device__ __align__(256) __half g_W2h[(size_t)DM * NRT];   // [768][10240]
__device__ __align__(256) __half g_Yh[(size_t)BATCH * NRT];
__device__ __align__(256) __half g_ENCh[128 * DM];          // 124 rows + 4 zero rows
__device__ __align__(256) float g_P[5ull * BATCH * DM];
__device__ float g_BIAS[NT];
__device__ __align__(16) float g_GATE[(size_t)BATCH * 128];
__device__ float g_PSQV[320];
__device__ float g_PSQU[320];
__device__ float g_PSABS[32 * 128];
__device__ float g_PCNT[32 * 128];

struct P5 { const float* p[5]; };

__device__ __forceinline__ void decode_t(int t, int& g, int& tl) {
    if (t < 4)       { g = 0; tl = t; }
    else if (t < 12) { g = 1; tl = t - 4; }
    else if (t < 28) { g = 2; tl = t - 12; }
    else if (t < 60) { g = 3; tl = t - 28; }
    else             { g = 4; tl = t - 60; }
}

__device__ __forceinline__ float blk_reduce256(float v) {
    __shared__ float sh[256];
    int tid = threadIdx.x;
    sh[tid] = v;
    __syncthreads();
    for (int s = 128; s > 0; s >>= 1) {
        if (tid < s) sh[tid] += sh[tid + s];
        __syncthreads();
    }
    float r = sh[0];
    __syncthreads();
    return r;
}

// ---- PTX helpers (baseline sm_80+ PTX only) ----
__device__ __forceinline__ uint32_t smem_u32(const void* p) {
    uint32_t a;
    asm("{ .reg .u64 t; cvta.to.shared.u64 t, %1; cvt.u32.u64 %0, t; }" : "=r"(a) : "l"(p));
    return a;
}
__device__ __forceinline__ void cp16(uint32_t dst, const void* src) {
    asm volatile("cp.async.cg.shared.global [%0], [%1], 16;" :: "r"(dst), "l"(src) : "memory");
}
__device__ __forceinline__ void mma_f16(float* d, const uint32_t* a, const uint32_t* b) {
    asm volatile("mma.sync.aligned.m16n8k16.row.col.f32.f16.f16.f32 "
        "{%0,%1,%2,%3}, {%4,%5,%6,%7}, {%8,%9}, {%0,%1,%2,%3};"
        : "+f"(d[0]), "+f"(d[1]), "+f"(d[2]), "+f"(d[3])
        : "r"(a[0]), "r"(a[1]), "r"(a[2]), "r"(a[3]), "r"(b[0]), "r"(b[1]));
}
__device__ __forceinline__ void ldsm_x4(uint32_t& r0, uint32_t& r1, uint32_t& r2, uint32_t& r3,
                                        uint32_t addr) {
    asm volatile("ldmatrix.sync.aligned.m8n8.x4.shared.b16 {%0,%1,%2,%3}, [%4];"
        : "=r"(r0), "=r"(r1), "=r"(r2), "=r"(r3) : "r"(addr));
}

// ============== prep kernels ==============
__global__ void prep_fused(P5 V, P5 E, P5 Bv) {
    int b = blockIdx.x;
    if (b < 7680) {
        int i4 = b * 256 + threadIdx.x;                // < 1966080
        int n = i4 / 192, kq = i4 % 192;
        int g = n >> 11, lr = n & 2047;
        float4 v = ((const float4*)V.p[g])[(size_t)lr * 192 + kq];
        __half2 h0 = __floats2half2_rn(v.x, v.y);
        __half2 h1 = __floats2half2_rn(v.z, v.w);
        uint2 r; r.x = *(uint32_t*)&h0; r.y = *(uint32_t*)&h1;
        ((uint2*)g_Vh)[(size_t)n * 192 + kq] = r;
    } else {
        int t = b - 7680;                              // 0..127
        if (t < NT) {
            int g, tl; decode_t(t, g, tl);
            const float* src = E.p[g] + (size_t)tl * DM;
            for (int i = threadIdx.x; i < DM; i += blockDim.x)
                g_ENCh[t * DM + i] = __float2half_rn(src[i]);
            if (threadIdx.x == 0) g_BIAS[t] = Bv.p[g][tl];
        } else {
            for (int i = threadIdx.x; i < DM; i += blockDim.x)
                g_ENCh[t * DM + i] = __float2half_rn(0.f);
        }
    }
}

__global__ void rnd_x(const float* __restrict__ X) {
    int i4 = blockIdx.x * 256 + threadIdx.x;           // < 786432
    float4 v = ((const float4*)X)[i4];
    __half2 h0 = __floats2half2_rn(v.x, v.y);
    __half2 h1 = __floats2half2_rn(v.z, v.w);
    uint2 r; r.x = *(uint32_t*)&h0; r.y = *(uint32_t*)&h1;
    ((uint2*)g_Xh)[i4] = r;
}

__global__ void build_w2(P5 U) {
    int g = blockIdx.y;
    int r = 512 >> g;
    int rq = r >> 2;
    int i4 = blockIdx.x * 256 + threadIdx.x;           // < 393216 per group
    int t = i4 / (DM * rq);
    int rem = i4 % (DM * rq);
    int d = rem / rq, jq = rem % rq;
    float4 v = ((const float4*)U.p[g])[(size_t)(t * DM + d) * rq + jq];
    __half2 h0 = __floats2half2_rn(v.x, v.y);
    __half2 h1 = __floats2half2_rn(v.z, v.w);
    uint2 rv; rv.x = *(uint32_t*)&h0; rv.y = *(uint32_t*)&h1;
    ((uint2*)g_W2h)[(size_t)d * 2560 + (g << 9) + t * rq + jq] = rv;
}

// ============== balanced norms: 320 segments of 32 rows ==============
__global__ void norms2(P5 V, P5 U) {
    int s = blockIdx.x;                   // 0..319
    int g = s >> 6, idx = s & 63;
    int nseg = 16 >> g;
    int tl = idx / nseg, seg = idx % nseg;
    int r = 512 >> g;
    const float4* v = (const float4*)(V.p[g] + ((size_t)tl * r + seg * 32) * DM);
    const float4* u = (const float4*)(U.p[g] + ((size_t)tl * r + seg * 32) * DM);
    float sv = 0.f, su = 0.f;
    for (int i = threadIdx.x; i < 32 * DM / 4; i += 256) {
        float4 a = v[i]; sv += a.x * a.x + a.y * a.y + a.z * a.z + a.w * a.w;
        float4 b = u[i]; su += b.x * b.x + b.y * b.y + b.z * b.z + b.w * b.w;
    }
    sv = blk_reduce256(sv);
    su = blk_reduce256(su);
    if (threadIdx.x == 0) { g_PSQV[s] = sv; g_PSQU[s] = su; }
}

// ============== coalesced gate stats: 32 blocks x 128 rows ==============
__global__ void gstat2() {
    int tid = threadIdx.x;
    int col = tid & 127, half = tid >> 7;
    int b0 = blockIdx.x * 128;
    float sa = 0.f, cnt = 0.f;
    for (int i = 0; i < 64; i++) {
        float gg = g_GATE[(size_t)(b0 + half + 2 * i) * 128 + col];
        sa += fabsf(gg);
        cnt += (gg > 0.f) ? 1.f : 0.f;
    }
    __shared__ float s1[256], s2[256];
    s1[tid] = sa; s2[tid] = cnt;
    __syncthreads();
    if (half == 0) {
        g_PSABS[blockIdx.x * 128 + col] = s1[tid] + s1[tid + 128];
        g_PCNT[blockIdx.x * 128 + col]  = s2[tid] + s2[tid + 128];
    }
}

__global__ void finalize_kernel(float* __restrict__ out) {
    int t = threadIdx.x;   // 128 threads
    float sp = 0.f, act = 0.f;
    if (t < NT) {
        int g, tl; decode_t(t, g, tl);
        int r = 512 >> g;
        int nseg = 16 >> g;
        int base = g * 64 + tl * nseg;
        float sqv = 0.f, squ = 0.f;
        for (int j = 0; j < nseg; j++) { sqv += g_PSQV[base + j]; squ += g_PSQU[base + j]; }
        float sa = 0.f, cnt = 0.f;
        for (int cck = 0; cck < 32; cck++) { sa += g_PSABS[cck * 128 + t]; cnt += g_PCNT[cck * 128 + t]; }
        float frob = sqrtf(squ * sqv) * rsqrtf((float)(DM * r));
        sp  = tanhf(sa / (float)BATCH) * frob;
        act = cnt;
    }
    __shared__ float s1[128], s2[128];
    s1[t] = sp; s2[t] = act;
    __syncthreads();
    for (int s = 64; s > 0; s >>= 1) {
        if (t < s) { s1[t] += s1[t + s]; s2[t] += s2[t + s]; }
        __syncthreads();
    }
    if (t == 0) {
        out[SP_OFF]  = s1[0];
        out[ACT_OFF] = s2[0] / (float)BATCH;
    }
}

// ============== fp16 mma.sync GEMMs (ldmatrix fragments) ==============
// MODE 1: Yh[m,n] = h( (Xh @ Vh^T)[m,n] * gate[m,t(n)] )   M=4096 N=10240 K=768
// MODE 2: P[z][m,d] = (Yh @ W2h^T)[m,d], K split 5x2048     M=4096 N=768
// MODE 3: gates = relu(Xh @ ENCh^T - b)
// BM=BN=128, BK=64, 256 thr, warp 64x32 (4x4 m16n8k16), 3-stage cp.async, 2 CTA/SM.
#define STGW 8192                 // 32-bit words per stage = 32KB
#define SMEMSZ (3 * STGW * 4)     // 96 KB

template<int MODE>
__global__ void __launch_bounds__(256, 2) gemm_mma(float* __restrict__ out) {
    extern __shared__ uint32_t sm[];
    const int Kdim = (MODE == 2) ? NRT : DM;
    const int NC   = (MODE == 2) ? 32 : 12;
    const __half* __restrict__ A = (MODE == 2) ? g_Yh : g_Xh;
    const __half* __restrict__ B = (MODE == 1) ? g_Vh : ((MODE == 2) ? g_W2h : g_ENCh);
    const int bm = blockIdx.y * 128;
    const int bn = blockIdx.x * 128;
    const int kb0 = (MODE == 2) ? blockIdx.z * 2048 : 0;
    const int tid = threadIdx.x;
    const int lane = tid & 31, w = tid >> 5;
    const int gq = lane >> 2, tig = lane & 3;
    const int wm = w & 1, wn = w >> 1;

    float c[4][4][4];
#pragma unroll
    for (int i = 0; i < 4; i++)
#pragma unroll
        for (int j = 0; j < 4; j++)
#pragma unroll
            for (int q = 0; q < 4; q++) c[i][j][q] = 0.f;

    const uint32_t smb = smem_u32(sm);

    // ldmatrix per-lane address bases (byte offsets within stage halves)
    // A x4 for mt tile: matrices (rows0-7,k0-7),(rows8-15,k0-7),(rows0-7,k8-15),(rows8-15,k8-15)
    const int lmrow = (lane >> 3) & 1;      // row-half of the matrix this lane addresses
    const int lmk   = lane >> 4;            // k-half
    uint32_t rowA[4]; int swA[4];
#pragma unroll
    for (int mt = 0; mt < 4; mt++) {
        int row = wm * 64 + mt * 16 + lmrow * 8 + (lane & 7);
        rowA[mt] = (uint32_t)(row * 128);
        swA[mt]  = row & 7;
    }
    // B x4 for nt pair (2j, 2j+1): matrices (nt,k0-7),(nt,k8-15),(nt+1,k0-7),(nt+1,k8-15)
    const int lmkB = (lane >> 3) & 1;       // k-half for B
    uint32_t rowB[2]; int swB[2];
#pragma unroll
    for (int j = 0; j < 2; j++) {
        int row = wn * 32 + (2 * j + (lane >> 4)) * 8 + (lane & 7);
        rowB[j] = (uint32_t)(row * 128);
        swB[j]  = row & 7;
    }

#define LOAD_STAGE(s, cidx) do { \
    uint32_t stb = smb + (uint32_t)(s) * (STGW * 4); \
    int kb = kb0 + (cidx) * 64; \
    _Pragma("unroll") \
    for (int t_ = 0; t_ < 8; t_++) { \
        int idx = tid + t_ * 256; \
        int isB = idx >> 10, rem = idx & 1023; \
        int row = rem >> 3, u = rem & 7; \
        uint32_t dst = stb + (uint32_t)(isB * 16384 + row * 128 + ((u ^ (row & 7)) << 4)); \
        const __half* src = (isB ? B + (size_t)(bn + row) * Kdim : A + (size_t)(bm + row) * Kdim) + kb + u * 8; \
        cp16(dst, src); \
    } \
    asm volatile("cp.async.commit_group;" ::: "memory"); \
} while (0)

    LOAD_STAGE(0, 0);
    LOAD_STAGE(1, 1);

    for (int i = 0; i < NC; i++) {
        asm volatile("cp.async.wait_group 1;" ::: "memory");
        __syncthreads();
        if (i + 2 < NC) {
            LOAD_STAGE((i + 2) % 3, i + 2);
        } else {
            asm volatile("cp.async.commit_group;" ::: "memory");
        }
        const uint32_t stA = smb + (uint32_t)(i % 3) * (STGW * 4);
        const uint32_t stB = stA + 16384u;
#pragma unroll
        for (int ks = 0; ks < 4; ks++) {
            uint32_t a[4][4], b[4][2];
#pragma unroll
            for (int mt = 0; mt < 4; mt++)
                ldsm_x4(a[mt][0], a[mt][1], a[mt][2], a[mt][3],
                        stA + rowA[mt] + (uint32_t)((((2 * ks + lmk) ^ swA[mt])) << 4));
#pragma unroll
            for (int j = 0; j < 2; j++)
                ldsm_x4(b[2 * j][0], b[2 * j][1], b[2 * j + 1][0], b[2 * j + 1][1],
                        stB + rowB[j] + (uint32_t)((((2 * ks + lmkB) ^ swB[j])) << 4));
#pragma unroll
            for (int mt = 0; mt < 4; mt++)
#pragma unroll
                for (int nt = 0; nt < 4; nt++)
                    mma_f16(c[mt][nt], a[mt], b[nt]);
        }
    }

    // epilogue: c[mt][nt][q] -> row = bm+wm*64+mt*16+gq+(q>>1)*8, col = bn+wn*32+nt*8+2*tig+(q&1)
    if (MODE == 1) {
#pragma unroll
        for (int mt = 0; mt < 4; mt++) {
#pragma unroll
            for (int rr = 0; rr < 2; rr++) {
                int m = bm + wm * 64 + mt * 16 + gq + rr * 8;
                const float* grow = g_GATE + (size_t)m * 128;
                __half* yrow = g_Yh + (size_t)m * NRT;
#pragma unroll
                for (int nt = 0; nt < 4; nt++) {
                    int colg = bn + wn * 32 + nt * 8 + 2 * tig;
                    int gg = colg >> 11;
                    int t = c_tbase[gg] + ((colg & 2047) >> c_shift[gg]);
                    float gv = grow[t];
                    *(__half2*)(yrow + colg) =
                        __floats2half2_rn(c[mt][nt][rr * 2 + 0] * gv, c[mt][nt][rr * 2 + 1] * gv);
                }
            }
        }
    } else if (MODE == 2) {
        float* P = g_P + (size_t)blockIdx.z * ((size_t)BATCH * DM);
#pragma unroll
        for (int mt = 0; mt < 4; mt++) {
#pragma unroll
            for (int rr = 0; rr < 2; rr++) {
                int m = bm + wm * 64 + mt * 16 + gq + rr * 8;
                float* prow = P + (size_t)m * DM;
#pragma unroll
                for (int nt = 0; nt < 4; nt++) {
                    int colg = bn + wn * 32 + nt * 8 + 2 * tig;
                    *(float2*)(prow + colg) =
                        make_float2(c[mt][nt][rr * 2 + 0], c[mt][nt][rr * 2 + 1]);
                }
            }
        }
    } else {
#pragma unroll
        for (int mt = 0; mt < 4; mt++) {
#pragma unroll
            for (int rr = 0; rr < 2; rr++) {
                int m = bm + wm * 64 + mt * 16 + gq + rr * 8;
#pragma unroll
                for (int nt = 0; nt < 4; nt++) {
#pragma unroll
                    for (int e = 0; e < 2; e++) {
                        int t = wn * 32 + nt * 8 + 2 * tig + e;
                        if (t < NT) {
                            float pre = c[mt][nt][rr * 2 + e] - g_BIAS[t];
                            float gv = pre > 0.f ? pre : 0.f;
                            g_GATE[(size_t)m * 128 + t] = gv;
                            int gg, tl; decode_t(t, gg, tl);
                            out[c_goff[gg] + (size_t)m * c_n[gg] + tl] = gv;
                        }
                    }
                }
            }
        }
    }
}

__global__ void sum5_kernel(float* __restrict__ OUT) {
    size_t i = (size_t)blockIdx.x * 256 + threadIdx.x;   // < 786432
    const size_t N4 = (size_t)BATCH * DM / 4;
    const float4* p = (const float4*)g_P;
    float4 a = p[i], b = p[i + N4], c = p[i + 2 * N4], d = p[i + 3 * N4], e = p[i + 4 * N4];
    ((float4*)OUT)[i] = make_float4(a.x + b.x + c.x + d.x + e.x, a.y + b.y + c.y + d.y + e.y,
                                    a.z + b.z + c.z + d.z + e.z, a.w + b.w + c.w + d.w + e.w);
}

// ============== launch ==============
extern "C" void kernel_launch(void* const* d_in, const int* in_sizes, int n_in,
                              void* d_out, int out_size) {
    (void)in_sizes; (void)n_in; (void)out_size;
    const float* x = (const float*)d_in[0];
    P5 V, U, E, Bv;
    for (int g = 0; g < 5; g++) {
        V.p[g]  = (const float*)d_in[1 + 4 * g];
        U.p[g]  = (const float*)d_in[2 + 4 * g];
        E.p[g]  = (const float*)d_in[3 + 4 * g];
        Bv.p[g] = (const float*)d_in[4 + 4 * g];
    }
    float* out = (float*)d_out;

    cudaFuncSetAttribute(gemm_mma<1>, cudaFuncAttributeMaxDynamicSharedMemorySize, SMEMSZ);
    cudaFuncSetAttribute(gemm_mma<2>, cudaFuncAttributeMaxDynamicSharedMemorySize, SMEMSZ);
    cudaFuncSetAttribute(gemm_mma<3>, cudaFuncAttributeMaxDynamicSharedMemorySize, SMEMSZ);

    prep_fused<<<7808, 256>>>(V, E, Bv);                         // 0
    rnd_x<<<3072, 256>>>(x);                                     // 1
    gemm_mma<3><<<dim3(1, BATCH / 128), 256, SMEMSZ>>>(out);     // 2: gates
    gemm_mma<1><<<dim3(NRT / 128, BATCH / 128), 256, SMEMSZ>>>(out); // 3: ncu slot
    build_w2<<<dim3(1536, 5), 256>>>(U);                         // 4
    norms2<<<320, 256>>>(V, U);                                  // 5
    gstat2<<<32, 256>>>();                                       // 6
    finalize_kernel<<<1, 128>>>(out);                            // 7
    gemm_mma<2><<<dim3(DM / 128, BATCH / 128, 5), 256, SMEMSZ>>>(out); // 8
    sum5_kernel<<<3072, 256>>>(out);                             // 9
}